// round 8
// baseline (speedup 1.0000x reference)
#include <cuda_runtime.h>
#include <cuda_bf16.h>
#include <cstdint>

#define TOK   256
#define INF   4096
#define OUTF  4096
#define NOUT  32

#define BM 128
#define BN 128          // 64 tensor + 64 dp4a
#define BK 128
#define KSPLIT 4
#define NCH_PER (INF / BK / KSPLIT)   // 8 k-chunks per CTA
#define STAGES 4

#define ABLK 16384      // 128 m x 128 k int8, swizzled
#define BBLK 16384      // 128 n x 128 k int8, swizzled

// ---------------- scratch (no cudaMalloc allowed) ----------------
__device__ __align__(128) int8_t g_xq[TOK * INF];          // A blocks (1MB)
__device__ __align__(128) int8_t g_w8[(size_t)OUTF * INF]; // B blocks (16MB)
__device__ float g_xs[TOK];
__device__ float g_xout[TOK * NOUT];

__device__ __forceinline__ uint32_t smem_to_u32(const void* p) {
    uint32_t a;
    asm("{ .reg .u64 t; cvta.to.shared.u64 t, %1; cvt.u32.u64 %0, t; }" : "=r"(a) : "l"(p));
    return a;
}

#define MBARRIER_INIT(mbar, count) \
    asm volatile("mbarrier.init.shared.b64 [%0], %1;" :: "r"((uint32_t)(mbar)), "r"((uint32_t)(count)) : "memory")
#define MBARRIER_EXPECT_TX(mbar, bytes) \
    asm volatile("mbarrier.arrive.expect_tx.shared.b64 _, [%0], %1;" :: "r"((uint32_t)(mbar)), "r"((uint32_t)(bytes)) : "memory")
#define BULK_G2S(dst, src, bytes, mbar) \
    asm volatile("cp.async.bulk.shared::cluster.global.mbarrier::complete_tx::bytes [%0], [%1], %2, [%3];" \
        :: "r"((uint32_t)(dst)), "l"(src), "r"((uint32_t)(bytes)), "r"((uint32_t)(mbar)) : "memory")

#define MBARRIER_WAIT_PARITY(mbar_smem_addr, phase_parity) do { \
    uint32_t _mbar = (uint32_t)(mbar_smem_addr); \
    uint32_t _parity = (uint32_t)(phase_parity); \
    uint32_t _done; \
    asm volatile("{\n\t.reg .pred p;\n\t" \
        "mbarrier.try_wait.parity.acquire.cta.shared::cta.b64 p, [%1], %2;\n\t" \
        "selp.b32 %0, 1, 0, p;\n\t}" : "=r"(_done) : "r"(_mbar), "r"(_parity) : "memory"); \
    if (!_done) { \
        asm volatile("{\n\t.reg .pred P1;\n\t" \
            "WAIT_LOOP_%=:\n\t" \
            "mbarrier.try_wait.parity.acquire.cta.shared::cta.b64 P1, [%0], %1, 0x989680;\n\t" \
            "@P1 bra.uni WAIT_DONE_%=;\n\t" \
            "bra.uni WAIT_LOOP_%=;\n\t" \
            "WAIT_DONE_%=:\n\t}" :: "r"(_mbar), "r"(_parity) : "memory"); \
    } \
} while (0)

// ---------------- rowwise quantize + mask fuse + outlier gather ----------------
__global__ __launch_bounds__(256) void quantize_kernel(const float* __restrict__ x,
                                                       const int* __restrict__ oidx) {
    const int r = blockIdx.x;
    const int tid = threadIdx.x;
    const int wid = tid >> 5, lid = tid & 31;
    __shared__ int   s_oi[NOUT];
    __shared__ float red[8];
    __shared__ float s_scale;

    const float4* xr = (const float4*)(x + (size_t)r * INF);
    float4 f[4];
#pragma unroll
    for (int t = 0; t < 4; t++) f[t] = xr[tid * 4 + t];

    if (tid < NOUT) s_oi[tid] = oidx[tid];
    __syncthreads();

    const int kbase = tid * 16;
    unsigned mz = 0;
#pragma unroll
    for (int j = 0; j < NOUT; j++) {
        unsigned d = (unsigned)(s_oi[j] - kbase);
        if (d < 16u) mz |= 1u << d;
    }
#pragma unroll
    for (int t = 0; t < 4; t++) {
        if (mz & (1u << (t * 4 + 0))) f[t].x = 0.0f;
        if (mz & (1u << (t * 4 + 1))) f[t].y = 0.0f;
        if (mz & (1u << (t * 4 + 2))) f[t].z = 0.0f;
        if (mz & (1u << (t * 4 + 3))) f[t].w = 0.0f;
    }

    float mx = 0.0f;
#pragma unroll
    for (int t = 0; t < 4; t++)
        mx = fmaxf(mx, fmaxf(fmaxf(fabsf(f[t].x), fabsf(f[t].y)),
                             fmaxf(fabsf(f[t].z), fabsf(f[t].w))));
#pragma unroll
    for (int d = 16; d > 0; d >>= 1) mx = fmaxf(mx, __shfl_xor_sync(0xFFFFFFFFu, mx, d));
    if (lid == 0) red[wid] = mx;
    __syncthreads();
    if (tid == 0) {
        float m = red[0];
#pragma unroll
        for (int i = 1; i < 8; i++) m = fmaxf(m, red[i]);
        s_scale = m;
        g_xs[r] = m;
    }
    __syncthreads();
    const float r127 = 127.0f / fmaxf(s_scale, 1e-8f);

    uint32_t pk[4];
#pragma unroll
    for (int t = 0; t < 4; t++) {
        int q0 = min(max(__float2int_rn(f[t].x * r127), -127), 127);
        int q1 = min(max(__float2int_rn(f[t].y * r127), -127), 127);
        int q2 = min(max(__float2int_rn(f[t].z * r127), -127), 127);
        int q3 = min(max(__float2int_rn(f[t].w * r127), -127), 127);
        uint32_t p0 = __byte_perm((uint32_t)q0, (uint32_t)q1, 0x0040);
        uint32_t p1 = __byte_perm((uint32_t)q2, (uint32_t)q3, 0x0040);
        pk[t] = __byte_perm(p0, p1, 0x5410);
    }
    const int mt = r >> 7, rr = r & 127;
    const int c = tid >> 3, cp = tid & 7;
    int8_t* dst = g_xq + ((size_t)(mt * 32 + c) << 14) + rr * 128 + (((cp ^ (rr & 7))) << 4);
    *(uint4*)dst = make_uint4(pk[0], pk[1], pk[2], pk[3]);

    if (tid < NOUT) {
        g_xout[r * NOUT + tid] = x[(size_t)r * INF + s_oi[tid]];
    }
}

// ---------------- prepack: w int32 -> blocked-swizzled int8 (16KB blocks) ----------------
// block (nt2 in [0,32), c in [0,32)): rows nt2*128..+128, k-chunk c -> 16KB
__global__ __launch_bounds__(256) void pack_w_kernel(const int* __restrict__ w) {
    const int nt2 = blockIdx.x >> 5, c = blockIdx.x & 31;
    const int tid = threadIdx.x;
#pragma unroll
    for (int t = 0; t < 4; t++) {
        int u = tid + t * 256;           // [0,1024): r = u>>3, cc = u&7
        int r = u >> 3, cc = u & 7;
        const int* src = w + (size_t)(nt2 * 128 + r) * INF + c * 128 + cc * 16;
        int4 v0 = *(const int4*)(src);
        int4 v1 = *(const int4*)(src + 4);
        int4 v2 = *(const int4*)(src + 8);
        int4 v3 = *(const int4*)(src + 12);
        uint32_t a0 = __byte_perm(__byte_perm((uint32_t)v0.x, (uint32_t)v0.y, 0x0040),
                                  __byte_perm((uint32_t)v0.z, (uint32_t)v0.w, 0x0040), 0x5410);
        uint32_t a1 = __byte_perm(__byte_perm((uint32_t)v1.x, (uint32_t)v1.y, 0x0040),
                                  __byte_perm((uint32_t)v1.z, (uint32_t)v1.w, 0x0040), 0x5410);
        uint32_t a2 = __byte_perm(__byte_perm((uint32_t)v2.x, (uint32_t)v2.y, 0x0040),
                                  __byte_perm((uint32_t)v2.z, (uint32_t)v2.w, 0x0040), 0x5410);
        uint32_t a3 = __byte_perm(__byte_perm((uint32_t)v3.x, (uint32_t)v3.y, 0x0040),
                                  __byte_perm((uint32_t)v3.z, (uint32_t)v3.w, 0x0040), 0x5410);
        int8_t* dst = g_w8 + ((size_t)(nt2 * 32 + c) << 14) + r * 128 + ((cc ^ (r & 7)) << 4);
        *(uint4*)dst = make_uint4(a0, a1, a2, a3);
    }
}

// ---------------- outlier GEMM + bias -> out (prefill) ----------------
__global__ __launch_bounds__(256) void outlier_bias_kernel(const float* __restrict__ ow,
                                                           const float* __restrict__ bias,
                                                           float* __restrict__ out) {
    __shared__ float s_owT[NOUT * 128];  // [j][o]
    __shared__ float s_x[32 * NOUT];     // [t][j]
    __shared__ float s_b[128];

    const int tid = threadIdx.x;
    const int obase = blockIdx.x * 128;
    const int tbase = blockIdx.y * 32;

    if (tid < 128) s_b[tid] = bias[obase + tid];

#pragma unroll
    for (int t = 0; t < 4; t++) {
        int i = tid + t * 256;
        int o = i >> 3, j4 = i & 7;
        float4 f = ((const float4*)ow)[(size_t)obase * 8 + i];
        s_owT[(j4 * 4 + 0) * 128 + o] = f.x;
        s_owT[(j4 * 4 + 1) * 128 + o] = f.y;
        s_owT[(j4 * 4 + 2) * 128 + o] = f.z;
        s_owT[(j4 * 4 + 3) * 128 + o] = f.w;
    }
    ((float4*)s_x)[tid] = ((const float4*)(g_xout + tbase * NOUT))[tid];
    __syncthreads();

    const int ty = tid >> 5, tx = tid & 31;
    float acc[4][4];
#pragma unroll
    for (int tt = 0; tt < 4; tt++)
#pragma unroll
        for (int c = 0; c < 4; c++) acc[tt][c] = s_b[tx + c * 32];

#pragma unroll
    for (int j = 0; j < NOUT; j++) {
        float wv[4];
#pragma unroll
        for (int c = 0; c < 4; c++) wv[c] = s_owT[j * 128 + tx + c * 32];
#pragma unroll
        for (int tt = 0; tt < 4; tt++) {
            float xv = s_x[(ty * 4 + tt) * NOUT + j];
#pragma unroll
            for (int c = 0; c < 4; c++) acc[tt][c] += xv * wv[c];
        }
    }
#pragma unroll
    for (int tt = 0; tt < 4; tt++)
#pragma unroll
        for (int c = 0; c < 4; c++)
            out[(size_t)(tbase + ty * 4 + tt) * OUTF + obase + tx + c * 32] = acc[tt][c];
}

// ---------------- hybrid GEMM: IMMA warps (n 0..64) + dp4a warps (n 64..128) ----------------
// 768 threads: warps 0-7 tensor (proven 4m x 2n core), warps 8-23 dp4a.
// 4-stage bulk pipeline, 128KB smem, 1 CTA/SM.
#define SA_OFF(s) ((s) * 32768)
#define SB_OFF(s) ((s) * 32768 + 16384)
#define MB_OFF    131072
#define SMEM_TOTAL (131072 + 128)

__global__ __launch_bounds__(768, 1) void gemm_kernel(const float* __restrict__ wscale,
                                                      float* __restrict__ out) {
    extern __shared__ char smem[];
    const uint32_t sb = smem_to_u32(smem);
    const int tid = threadIdx.x;
    const int lane = tid & 31, wid = tid >> 5;
    const int nt = blockIdx.x;                // 32 n-tiles of 128
    const int mt = blockIdx.y;                // 2 m-tiles
    const int kz = blockIdx.z;                // 4 k-splits

    const int8_t* Asrc = g_xq + ((size_t)(mt * 32 + kz * NCH_PER) << 14);
    const int8_t* Bsrc = g_w8 + ((size_t)(nt * 32 + kz * NCH_PER) << 14);

    if (tid == 0) {
#pragma unroll
        for (int s = 0; s < STAGES; s++) MBARRIER_INIT(sb + MB_OFF + s * 8, 1);
    }
    __syncthreads();

    if (tid == 0) {
#pragma unroll
        for (int s = 0; s < 3; s++) {
            const uint32_t mb = sb + MB_OFF + s * 8;
            MBARRIER_EXPECT_TX(mb, ABLK + BBLK);
            BULK_G2S(sb + SA_OFF(s), Asrc + (size_t)s * ABLK, ABLK, mb);
            BULK_G2S(sb + SB_OFF(s), Bsrc + (size_t)s * BBLK, BBLK, mb);
        }
    }

    int acc[32];
#pragma unroll
    for (int i = 0; i < 32; i++) acc[i] = 0;

    // dp4a thread geometry (valid for wid >= 8)
    const int dt = tid - 256;                 // 0..511
    const int tmq = dt >> 4;                  // 0..31 -> m rows tmq*4..+4
    const int tnq = dt & 15;                  // 0..15 -> n rows 64+tnq*4..+4

#pragma unroll 1
    for (int c = 0; c < NCH_PER; c++) {
        const int s = c & (STAGES - 1);
        const int ph = (c >> 2) & 1;
        MBARRIER_WAIT_PARITY(sb + MB_OFF + s * 8, ph);

        if (tid == 0 && c + 3 < NCH_PER) {
            const int fs = (c + 3) & (STAGES - 1);
            const uint32_t mb = sb + MB_OFF + fs * 8;
            MBARRIER_EXPECT_TX(mb, ABLK + BBLK);
            BULK_G2S(sb + SA_OFF(fs), Asrc + (size_t)(c + 3) * ABLK, ABLK, mb);
            BULK_G2S(sb + SB_OFF(fs), Bsrc + (size_t)(c + 3) * BBLK, BBLK, mb);
        }

        if (wid < 8) {
            // ---- tensor warps: proven IMMA core on n[0:64) ----
            const int wm = wid >> 1, wn = wid & 1;
#pragma unroll
            for (int ksl = 0; ksl < 4; ksl++) {
                uint32_t a[2][4];
#pragma unroll
                for (int mf = 0; mf < 2; mf++) {
                    int row = wm * 32 + mf * 16 + (lane & 15);
                    int kc = 2 * ksl + (lane >> 4);
                    uint32_t ad = sb + SA_OFF(s) +
                                  (uint32_t)(row * 128 + ((kc ^ (row & 7)) << 4));
                    asm volatile("ldmatrix.sync.aligned.m8n8.x4.shared.b16 {%0,%1,%2,%3}, [%4];"
                        : "=r"(a[mf][0]), "=r"(a[mf][1]), "=r"(a[mf][2]), "=r"(a[mf][3])
                        : "r"(ad));
                }
                uint32_t b[2][4];
#pragma unroll
                for (int np = 0; np < 2; np++) {
                    int n = wn * 32 + np * 16 + (lane & 7) + ((lane >> 4) << 3);
                    int kc = 2 * ksl + ((lane >> 3) & 1);
                    uint32_t bd = sb + SB_OFF(s) +
                                  (uint32_t)(n * 128 + ((kc ^ (n & 7)) << 4));
                    asm volatile("ldmatrix.sync.aligned.m8n8.x4.shared.b16 {%0,%1,%2,%3}, [%4];"
                        : "=r"(b[np][0]), "=r"(b[np][1]), "=r"(b[np][2]), "=r"(b[np][3])
                        : "r"(bd));
                }
#pragma unroll
                for (int mf = 0; mf < 2; mf++)
#pragma unroll
                    for (int nf = 0; nf < 4; nf++) {
                        uint32_t b0 = b[nf >> 1][(nf & 1) * 2];
                        uint32_t b1 = b[nf >> 1][(nf & 1) * 2 + 1];
                        int* ap = acc + (mf * 4 + nf) * 4;
                        asm volatile(
                            "mma.sync.aligned.m16n8k32.row.col.s32.s8.s8.s32 "
                            "{%0,%1,%2,%3}, {%4,%5,%6,%7}, {%8,%9}, {%0,%1,%2,%3};"
                            : "+r"(ap[0]), "+r"(ap[1]), "+r"(ap[2]), "+r"(ap[3])
                            : "r"(a[mf][0]), "r"(a[mf][1]), "r"(a[mf][2]), "r"(a[mf][3]),
                              "r"(b0), "r"(b1));
                    }
            }
        } else {
            // ---- dp4a warps: n[64:128) from the same swizzled tiles ----
            const char* As = smem + SA_OFF(s) + tmq * 4 * 128;
            const char* Bs = smem + SB_OFF(s) + (64 + tnq * 4) * 128;
            const int a7 = (tmq & 1) * 4;     // (tmq*4+mi)&7 = a7+mi
            const int b7 = (tnq & 1) * 4;     // (64+tnq*4+ni)&7 = b7+ni
#pragma unroll
            for (int g = 0; g < 8; g++) {
                int4 av[4], bv[4];
#pragma unroll
                for (int mi = 0; mi < 4; mi++)
                    av[mi] = *(const int4*)(As + mi * 128 + ((g ^ (a7 + mi)) << 4));
#pragma unroll
                for (int ni = 0; ni < 4; ni++)
                    bv[ni] = *(const int4*)(Bs + ni * 128 + ((g ^ (b7 + ni)) << 4));
#pragma unroll
                for (int mi = 0; mi < 4; mi++)
#pragma unroll
                    for (int ni = 0; ni < 4; ni++) {
                        int v = acc[mi * 4 + ni];
                        v = __dp4a(av[mi].x, bv[ni].x, v);
                        v = __dp4a(av[mi].y, bv[ni].y, v);
                        v = __dp4a(av[mi].z, bv[ni].z, v);
                        v = __dp4a(av[mi].w, bv[ni].w, v);
                        acc[mi * 4 + ni] = v;
                    }
            }
        }
        __syncthreads();
    }

    // ---- epilogue: atomicAdd partial = s32 * (xs*ws/127^2) onto prefilled out ----
    const float inv = 1.0f / 16129.0f;
    const int nbase = nt * BN, mbase = mt * BM;
    if (wid < 8) {
        const int wm = wid >> 1, wn = wid & 1;
        const int grp = lane >> 2, qid = lane & 3;
#pragma unroll
        for (int mf = 0; mf < 2; mf++) {
            const int m0 = mbase + wm * 32 + mf * 16 + grp;
            const float s0 = g_xs[m0] * inv;
            const float s1 = g_xs[m0 + 8] * inv;
#pragma unroll
            for (int nf = 0; nf < 4; nf++) {
                const int o = nbase + wn * 32 + nf * 8 + qid * 2;
                const float2 wsv = *(const float2*)(wscale + o);
                const int* ap = acc + (mf * 4 + nf) * 4;
                float* p0 = out + (size_t)m0 * OUTF + o;
                float* p1 = out + (size_t)(m0 + 8) * OUTF + o;
                atomicAdd(p0,     (float)ap[0] * (s0 * wsv.x));
                atomicAdd(p0 + 1, (float)ap[1] * (s0 * wsv.y));
                atomicAdd(p1,     (float)ap[2] * (s1 * wsv.x));
                atomicAdd(p1 + 1, (float)ap[3] * (s1 * wsv.y));
            }
        }
    } else {
        const int m0 = mbase + tmq * 4;
        const int o0 = nbase + 64 + tnq * 4;
        const float4 wsv = *(const float4*)(wscale + o0);
#pragma unroll
        for (int mi = 0; mi < 4; mi++) {
            const float smul = g_xs[m0 + mi] * inv;
            float* p = out + (size_t)(m0 + mi) * OUTF + o0;
            atomicAdd(p,     (float)acc[mi * 4 + 0] * (smul * wsv.x));
            atomicAdd(p + 1, (float)acc[mi * 4 + 1] * (smul * wsv.y));
            atomicAdd(p + 2, (float)acc[mi * 4 + 2] * (smul * wsv.z));
            atomicAdd(p + 3, (float)acc[mi * 4 + 3] * (smul * wsv.w));
        }
    }
}

// ---------------- launch: fork-join streams so pre-kernels overlap ----------------
extern "C" void kernel_launch(void* const* d_in, const int* in_sizes, int n_in,
                              void* d_out, int out_size) {
    const float* x    = (const float*)d_in[0];
    const int*   w    = (const int*)d_in[1];
    const float* ws   = (const float*)d_in[2];
    const int*   oidx = (const int*)d_in[3];
    const float* ow   = (const float*)d_in[4];
    const float* bias = (const float*)d_in[5];
    float* out = (float*)d_out;

    static cudaStream_t s1 = nullptr, s2 = nullptr;
    static cudaEvent_t e0 = nullptr, e1 = nullptr, e2 = nullptr;
    if (s1 == nullptr) {
        cudaStreamCreateWithFlags(&s1, cudaStreamNonBlocking);
        cudaStreamCreateWithFlags(&s2, cudaStreamNonBlocking);
        cudaEventCreateWithFlags(&e0, cudaEventDisableTiming);
        cudaEventCreateWithFlags(&e1, cudaEventDisableTiming);
        cudaEventCreateWithFlags(&e2, cudaEventDisableTiming);
        cudaFuncSetAttribute(gemm_kernel, cudaFuncAttributeMaxDynamicSharedMemorySize, SMEM_TOTAL);
    }

    cudaEventRecord(e0, 0);
    cudaStreamWaitEvent(s1, e0, 0);
    cudaStreamWaitEvent(s2, e0, 0);

    pack_w_kernel<<<32 * 32, 256, 0, s1>>>(w);
    quantize_kernel<<<TOK, 256, 0, s2>>>(x, oidx);
    outlier_bias_kernel<<<dim3(OUTF / 128, TOK / 32), 256, 0, s2>>>(ow, bias, out);

    cudaEventRecord(e1, s1);
    cudaEventRecord(e2, s2);
    cudaStreamWaitEvent(0, e1, 0);
    cudaStreamWaitEvent(0, e2, 0);

    gemm_kernel<<<dim3(OUTF / BN, TOK / BM, KSPLIT), 768, SMEM_TOTAL>>>(ws, out);
}

// round 10
// speedup vs baseline: 1.2242x; 1.2242x over previous
#include <cuda_runtime.h>
#include <cuda_bf16.h>
#include <cstdint>

#define TOK   256
#define INF   4096
#define OUTF  4096
#define NOUT  32

#define BM 128
#define BN 64
#define BK 128
#define KSPLIT 4
#define NCH_PER (INF / BK / KSPLIT)   // 8 k-chunks per CTA
#define STAGES 4

#define ABLK 16384      // 128 m x 128 k int8, swizzled
#define BBLK 8192       //  64 n x 128 k int8, swizzled

// ---------------- scratch (no cudaMalloc allowed) ----------------
__device__ __align__(128) int8_t g_xq[TOK * INF];          // A blocks (1MB)
__device__ __align__(128) int8_t g_w8[(size_t)OUTF * INF]; // B blocks (16MB)
__device__ float g_xs[TOK];

__device__ __forceinline__ uint32_t smem_to_u32(const void* p) {
    uint32_t a;
    asm("{ .reg .u64 t; cvta.to.shared.u64 t, %1; cvt.u32.u64 %0, t; }" : "=r"(a) : "l"(p));
    return a;
}

#define MBARRIER_INIT(mbar, count) \
    asm volatile("mbarrier.init.shared.b64 [%0], %1;" :: "r"((uint32_t)(mbar)), "r"((uint32_t)(count)) : "memory")
#define MBARRIER_ARRIVE(mbar) \
    asm volatile("mbarrier.arrive.shared.b64 _, [%0];" :: "r"((uint32_t)(mbar)) : "memory")
#define MBARRIER_EXPECT_TX(mbar, bytes) \
    asm volatile("mbarrier.arrive.expect_tx.shared.b64 _, [%0], %1;" :: "r"((uint32_t)(mbar)), "r"((uint32_t)(bytes)) : "memory")
#define BULK_G2S(dst, src, bytes, mbar) \
    asm volatile("cp.async.bulk.shared::cluster.global.mbarrier::complete_tx::bytes [%0], [%1], %2, [%3];" \
        :: "r"((uint32_t)(dst)), "l"(src), "r"((uint32_t)(bytes)), "r"((uint32_t)(mbar)) : "memory")

#define MBARRIER_WAIT_PARITY(mbar_smem_addr, phase_parity) do { \
    uint32_t _mbar = (uint32_t)(mbar_smem_addr); \
    uint32_t _parity = (uint32_t)(phase_parity); \
    uint32_t _done; \
    asm volatile("{\n\t.reg .pred p;\n\t" \
        "mbarrier.try_wait.parity.acquire.cta.shared::cta.b64 p, [%1], %2;\n\t" \
        "selp.b32 %0, 1, 0, p;\n\t}" : "=r"(_done) : "r"(_mbar), "r"(_parity) : "memory"); \
    if (!_done) { \
        asm volatile("{\n\t.reg .pred P1;\n\t" \
            "WAIT_LOOP_%=:\n\t" \
            "mbarrier.try_wait.parity.acquire.cta.shared::cta.b64 P1, [%0], %1, 0x989680;\n\t" \
            "@P1 bra.uni WAIT_DONE_%=;\n\t" \
            "bra.uni WAIT_LOOP_%=;\n\t" \
            "WAIT_DONE_%=:\n\t}" :: "r"(_mbar), "r"(_parity) : "memory"); \
    } \
} while (0)

// ---------------- rowwise quantize + mask fuse ----------------
__global__ __launch_bounds__(256) void quantize_kernel(const float* __restrict__ x,
                                                       const int* __restrict__ oidx) {
    const int r = blockIdx.x;
    const int tid = threadIdx.x;
    const int wid = tid >> 5, lid = tid & 31;
    __shared__ int   s_oi[NOUT];
    __shared__ float red[8];
    __shared__ float s_scale;

    const float4* xr = (const float4*)(x + (size_t)r * INF);
    float4 f[4];
#pragma unroll
    for (int t = 0; t < 4; t++) f[t] = xr[tid * 4 + t];

    if (tid < NOUT) s_oi[tid] = oidx[tid];
    __syncthreads();

    const int kbase = tid * 16;
    unsigned mz = 0;
#pragma unroll
    for (int j = 0; j < NOUT; j++) {
        unsigned d = (unsigned)(s_oi[j] - kbase);
        if (d < 16u) mz |= 1u << d;
    }
#pragma unroll
    for (int t = 0; t < 4; t++) {
        if (mz & (1u << (t * 4 + 0))) f[t].x = 0.0f;
        if (mz & (1u << (t * 4 + 1))) f[t].y = 0.0f;
        if (mz & (1u << (t * 4 + 2))) f[t].z = 0.0f;
        if (mz & (1u << (t * 4 + 3))) f[t].w = 0.0f;
    }

    float mx = 0.0f;
#pragma unroll
    for (int t = 0; t < 4; t++)
        mx = fmaxf(mx, fmaxf(fmaxf(fabsf(f[t].x), fabsf(f[t].y)),
                             fmaxf(fabsf(f[t].z), fabsf(f[t].w))));
#pragma unroll
    for (int d = 16; d > 0; d >>= 1) mx = fmaxf(mx, __shfl_xor_sync(0xFFFFFFFFu, mx, d));
    if (lid == 0) red[wid] = mx;
    __syncthreads();
    if (tid == 0) {
        float m = red[0];
#pragma unroll
        for (int i = 1; i < 8; i++) m = fmaxf(m, red[i]);
        s_scale = m;
        g_xs[r] = m;
    }
    __syncthreads();
    const float r127 = 127.0f / fmaxf(s_scale, 1e-8f);

    uint32_t pk[4];
#pragma unroll
    for (int t = 0; t < 4; t++) {
        int q0 = min(max(__float2int_rn(f[t].x * r127), -127), 127);
        int q1 = min(max(__float2int_rn(f[t].y * r127), -127), 127);
        int q2 = min(max(__float2int_rn(f[t].z * r127), -127), 127);
        int q3 = min(max(__float2int_rn(f[t].w * r127), -127), 127);
        uint32_t p0 = __byte_perm((uint32_t)q0, (uint32_t)q1, 0x0040);
        uint32_t p1 = __byte_perm((uint32_t)q2, (uint32_t)q3, 0x0040);
        pk[t] = __byte_perm(p0, p1, 0x5410);
    }
    const int mt = r >> 7, rr = r & 127;
    const int c = tid >> 3, cp = tid & 7;
    int8_t* dst = g_xq + ((size_t)(mt * 32 + c) << 14) + rr * 128 + (((cp ^ (rr & 7))) << 4);
    *(uint4*)dst = make_uint4(pk[0], pk[1], pk[2], pk[3]);
}

// ---------------- prepack: w int32 -> blocked-swizzled int8 ----------------
// block (nt in [0,64), c in [0,32)): 64 o-rows x 128 k -> 8KB
__global__ __launch_bounds__(256) void pack_w_kernel(const int* __restrict__ w) {
    const int nt = blockIdx.x >> 5, c = blockIdx.x & 31;
    const int tid = threadIdx.x;
#pragma unroll
    for (int t = 0; t < 2; t++) {
        int u = tid + t * 256;           // [0,512): r = u>>3, cc = u&7
        int r = u >> 3, cc = u & 7;
        const int* src = w + (size_t)(nt * 64 + r) * INF + c * 128 + cc * 16;
        int4 v0 = *(const int4*)(src);
        int4 v1 = *(const int4*)(src + 4);
        int4 v2 = *(const int4*)(src + 8);
        int4 v3 = *(const int4*)(src + 12);
        uint32_t a0 = __byte_perm(__byte_perm((uint32_t)v0.x, (uint32_t)v0.y, 0x0040),
                                  __byte_perm((uint32_t)v0.z, (uint32_t)v0.w, 0x0040), 0x5410);
        uint32_t a1 = __byte_perm(__byte_perm((uint32_t)v1.x, (uint32_t)v1.y, 0x0040),
                                  __byte_perm((uint32_t)v1.z, (uint32_t)v1.w, 0x0040), 0x5410);
        uint32_t a2 = __byte_perm(__byte_perm((uint32_t)v2.x, (uint32_t)v2.y, 0x0040),
                                  __byte_perm((uint32_t)v2.z, (uint32_t)v2.w, 0x0040), 0x5410);
        uint32_t a3 = __byte_perm(__byte_perm((uint32_t)v3.x, (uint32_t)v3.y, 0x0040),
                                  __byte_perm((uint32_t)v3.z, (uint32_t)v3.w, 0x0040), 0x5410);
        int8_t* dst = g_w8 + ((size_t)(nt * 32 + c) << 13) + r * 128 + ((cc ^ (r & 7)) << 4);
        *(uint4*)dst = make_uint4(a0, a1, a2, a3);
    }
}

// ---------------- outlier GEMM + bias -> out (prefill, reads x directly) ----------------
__global__ __launch_bounds__(256) void outlier_bias_kernel(const float* __restrict__ x,
                                                           const int* __restrict__ oidx,
                                                           const float* __restrict__ ow,
                                                           const float* __restrict__ bias,
                                                           float* __restrict__ out) {
    __shared__ float s_owT[NOUT * 128];  // [j][o]
    __shared__ float s_x[32 * NOUT];     // [t][j]
    __shared__ float s_b[128];
    __shared__ int   s_oi[NOUT];

    const int tid = threadIdx.x;
    const int obase = blockIdx.x * 128;
    const int tbase = blockIdx.y * 32;

    if (tid < NOUT) s_oi[tid] = oidx[tid];
    if (tid < 128)  s_b[tid] = bias[obase + tid];
    __syncthreads();

#pragma unroll
    for (int t = 0; t < 4; t++) {
        int i = tid + t * 256;
        int o = i >> 3, j4 = i & 7;
        float4 f = ((const float4*)ow)[(size_t)obase * 8 + i];
        s_owT[(j4 * 4 + 0) * 128 + o] = f.x;
        s_owT[(j4 * 4 + 1) * 128 + o] = f.y;
        s_owT[(j4 * 4 + 2) * 128 + o] = f.z;
        s_owT[(j4 * 4 + 3) * 128 + o] = f.w;
    }
    // direct gather of 32x32 outlier values
#pragma unroll
    for (int t = 0; t < 4; t++) {
        int i = tid + t * 256;           // [0,1024)
        int r = i >> 5, j = i & 31;
        s_x[i] = x[(size_t)(tbase + r) * INF + s_oi[j]];
    }
    __syncthreads();

    const int ty = tid >> 5, tx = tid & 31;
    float acc[4][4];
#pragma unroll
    for (int tt = 0; tt < 4; tt++)
#pragma unroll
        for (int c = 0; c < 4; c++) acc[tt][c] = s_b[tx + c * 32];

#pragma unroll
    for (int j = 0; j < NOUT; j++) {
        float wv[4];
#pragma unroll
        for (int c = 0; c < 4; c++) wv[c] = s_owT[j * 128 + tx + c * 32];
#pragma unroll
        for (int tt = 0; tt < 4; tt++) {
            float xv = s_x[(ty * 4 + tt) * NOUT + j];
#pragma unroll
            for (int c = 0; c < 4; c++) acc[tt][c] += xv * wv[c];
        }
    }
#pragma unroll
    for (int tt = 0; tt < 4; tt++)
#pragma unroll
        for (int c = 0; c < 4; c++)
            out[(size_t)(tbase + ty * 4 + tt) * OUTF + obase + tx + c * 32] = acc[tt][c];
}

// ---------------- int8 GEMM: producer warp + full/empty mbarrier ring ----------------
// 288 threads: warps 0-7 consume (proven IMMA core), warp 8 = TMA producer.
// 4-stage ring, 96KB smem, 2 CTAs/SM.
#define SA_OFF(s) ((s) * 24576)
#define SB_OFF(s) ((s) * 24576 + 16384)
#define MBF_OFF   98304              // full[4]
#define MBE_OFF   (98304 + 32)       // empty[4]
#define SMEM_TOTAL (98304 + 128)

__global__ __launch_bounds__(288, 2) void gemm_kernel(const float* __restrict__ wscale,
                                                      float* __restrict__ out) {
    extern __shared__ char smem[];
    const uint32_t sb = smem_to_u32(smem);
    const int tid = threadIdx.x;
    const int lane = tid & 31, wid = tid >> 5;
    const int nt = blockIdx.x;                // 64 n-tiles
    const int mt = blockIdx.y;                // 2 m-tiles
    const int kz = blockIdx.z;                // 4 k-splits

    const int8_t* Asrc = g_xq + ((size_t)(mt * 32 + kz * NCH_PER) << 14);
    const int8_t* Bsrc = g_w8 + ((size_t)(nt * 32 + kz * NCH_PER) << 13);

    if (tid == 0) {
#pragma unroll
        for (int s = 0; s < STAGES; s++) {
            MBARRIER_INIT(sb + MBF_OFF + s * 8, 1);
            MBARRIER_INIT(sb + MBE_OFF + s * 8, 256);
        }
    }
    __syncthreads();

    if (wid == 8) {
        // ---- producer warp: issue all chunks, gated by empty ring ----
        if (lane == 0) {
#pragma unroll 1
            for (int f = 0; f < NCH_PER; f++) {
                const int fs = f & (STAGES - 1);
                if (f >= STAGES) {
                    MBARRIER_WAIT_PARITY(sb + MBE_OFF + fs * 8, ((f >> 2) - 1) & 1);
                }
                const uint32_t mb = sb + MBF_OFF + fs * 8;
                MBARRIER_EXPECT_TX(mb, ABLK + BBLK);
                BULK_G2S(sb + SA_OFF(fs), Asrc + (size_t)f * ABLK, ABLK, mb);
                BULK_G2S(sb + SB_OFF(fs), Bsrc + (size_t)f * BBLK, BBLK, mb);
            }
        }
    } else {
        // ---- consumer warps: proven IMMA core, per-stage full/empty gating ----
        const int wm = wid >> 1, wn = wid & 1;
        int acc[2][4][4];
#pragma unroll
        for (int i = 0; i < 2; i++)
#pragma unroll
            for (int j = 0; j < 4; j++)
#pragma unroll
                for (int k = 0; k < 4; k++) acc[i][j][k] = 0;

#pragma unroll 1
        for (int c = 0; c < NCH_PER; c++) {
            const int s = c & (STAGES - 1);
            MBARRIER_WAIT_PARITY(sb + MBF_OFF + s * 8, (c >> 2) & 1);

#pragma unroll
            for (int ksl = 0; ksl < 4; ksl++) {
                uint32_t a[2][4];
#pragma unroll
                for (int mf = 0; mf < 2; mf++) {
                    int row = wm * 32 + mf * 16 + (lane & 15);
                    int kc = 2 * ksl + (lane >> 4);
                    uint32_t ad = sb + SA_OFF(s) +
                                  (uint32_t)(row * 128 + ((kc ^ (row & 7)) << 4));
                    asm volatile("ldmatrix.sync.aligned.m8n8.x4.shared.b16 {%0,%1,%2,%3}, [%4];"
                        : "=r"(a[mf][0]), "=r"(a[mf][1]), "=r"(a[mf][2]), "=r"(a[mf][3])
                        : "r"(ad));
                }
                uint32_t b[2][4];
#pragma unroll
                for (int np = 0; np < 2; np++) {
                    int n = wn * 32 + np * 16 + (lane & 7) + ((lane >> 4) << 3);
                    int kc = 2 * ksl + ((lane >> 3) & 1);
                    uint32_t bd = sb + SB_OFF(s) +
                                  (uint32_t)(n * 128 + ((kc ^ (n & 7)) << 4));
                    asm volatile("ldmatrix.sync.aligned.m8n8.x4.shared.b16 {%0,%1,%2,%3}, [%4];"
                        : "=r"(b[np][0]), "=r"(b[np][1]), "=r"(b[np][2]), "=r"(b[np][3])
                        : "r"(bd));
                }
#pragma unroll
                for (int mf = 0; mf < 2; mf++)
#pragma unroll
                    for (int nf = 0; nf < 4; nf++) {
                        uint32_t b0 = b[nf >> 1][(nf & 1) * 2];
                        uint32_t b1 = b[nf >> 1][(nf & 1) * 2 + 1];
                        asm volatile(
                            "mma.sync.aligned.m16n8k32.row.col.s32.s8.s8.s32 "
                            "{%0,%1,%2,%3}, {%4,%5,%6,%7}, {%8,%9}, {%0,%1,%2,%3};"
                            : "+r"(acc[mf][nf][0]), "+r"(acc[mf][nf][1]),
                              "+r"(acc[mf][nf][2]), "+r"(acc[mf][nf][3])
                            : "r"(a[mf][0]), "r"(a[mf][1]), "r"(a[mf][2]), "r"(a[mf][3]),
                              "r"(b0), "r"(b1));
                    }
            }
            MBARRIER_ARRIVE(sb + MBE_OFF + s * 8);   // done reading stage s
        }

        // ---- epilogue: atomicAdd partial = s32 * (xs*ws/127^2) onto prefilled out ----
        const float inv = 1.0f / 16129.0f;
        const int grp = lane >> 2, qid = lane & 3;
        const int nbase = nt * BN, mbase = mt * BM;
#pragma unroll
        for (int mf = 0; mf < 2; mf++) {
            const int m0 = mbase + wm * 32 + mf * 16 + grp;
            const float s0 = g_xs[m0] * inv;
            const float s1 = g_xs[m0 + 8] * inv;
#pragma unroll
            for (int nf = 0; nf < 4; nf++) {
                const int o = nbase + wn * 32 + nf * 8 + qid * 2;
                const float2 wsv = *(const float2*)(wscale + o);
                float* p0 = out + (size_t)m0 * OUTF + o;
                float* p1 = out + (size_t)(m0 + 8) * OUTF + o;
                atomicAdd(p0,     (float)acc[mf][nf][0] * (s0 * wsv.x));
                atomicAdd(p0 + 1, (float)acc[mf][nf][1] * (s0 * wsv.y));
                atomicAdd(p1,     (float)acc[mf][nf][2] * (s1 * wsv.x));
                atomicAdd(p1 + 1, (float)acc[mf][nf][3] * (s1 * wsv.y));
            }
        }
    }
}

// ---------------- launch: default stream only (no stream/event creation) ----------------
extern "C" void kernel_launch(void* const* d_in, const int* in_sizes, int n_in,
                              void* d_out, int out_size) {
    const float* x    = (const float*)d_in[0];
    const int*   w    = (const int*)d_in[1];
    const float* ws   = (const float*)d_in[2];
    const int*   oidx = (const int*)d_in[3];
    const float* ow   = (const float*)d_in[4];
    const float* bias = (const float*)d_in[5];
    float* out = (float*)d_out;

    cudaFuncSetAttribute(gemm_kernel, cudaFuncAttributeMaxDynamicSharedMemorySize, SMEM_TOTAL);

    quantize_kernel<<<TOK, 256>>>(x, oidx);
    pack_w_kernel<<<64 * 32, 256>>>(w);
    outlier_bias_kernel<<<dim3(OUTF / 128, TOK / 32), 256>>>(x, oidx, ow, bias, out);
    gemm_kernel<<<dim3(OUTF / BN, TOK / BM, KSPLIT), 288, SMEM_TOTAL>>>(ws, out);
}

// round 11
// speedup vs baseline: 1.3747x; 1.1230x over previous
#include <cuda_runtime.h>
#include <cuda_bf16.h>
#include <cstdint>

#define TOK   256
#define INF   4096
#define OUTF  4096
#define NOUT  32

#define BM 128
#define BN 64
#define BK 128
#define NCHU 32                 // chunks per (nt,mt) tile
#define NTILES 128              // 64 nt x 2 mt
#define TOTCH (NTILES * NCHU)   // 4096 flattened chunk-units
#define NCTA 296                // 148 SMs x 2 resident
#define STAGES 4

#define ABLK 16384      // 128 m x 128 k int8, swizzled
#define BBLK 8192       //  64 n x 128 k int8, swizzled

// ---------------- scratch (no cudaMalloc allowed) ----------------
__device__ __align__(128) int8_t g_xq[TOK * INF];          // A blocks (1MB)
__device__ __align__(128) int8_t g_w8[(size_t)OUTF * INF]; // B blocks (16MB)
__device__ float g_xs[TOK];

__device__ __forceinline__ uint32_t smem_to_u32(const void* p) {
    uint32_t a;
    asm("{ .reg .u64 t; cvta.to.shared.u64 t, %1; cvt.u32.u64 %0, t; }" : "=r"(a) : "l"(p));
    return a;
}

#define MBARRIER_INIT(mbar, count) \
    asm volatile("mbarrier.init.shared.b64 [%0], %1;" :: "r"((uint32_t)(mbar)), "r"((uint32_t)(count)) : "memory")
#define MBARRIER_ARRIVE(mbar) \
    asm volatile("mbarrier.arrive.shared.b64 _, [%0];" :: "r"((uint32_t)(mbar)) : "memory")
#define MBARRIER_EXPECT_TX(mbar, bytes) \
    asm volatile("mbarrier.arrive.expect_tx.shared.b64 _, [%0], %1;" :: "r"((uint32_t)(mbar)), "r"((uint32_t)(bytes)) : "memory")
#define BULK_G2S(dst, src, bytes, mbar) \
    asm volatile("cp.async.bulk.shared::cluster.global.mbarrier::complete_tx::bytes [%0], [%1], %2, [%3];" \
        :: "r"((uint32_t)(dst)), "l"(src), "r"((uint32_t)(bytes)), "r"((uint32_t)(mbar)) : "memory")

#define MBARRIER_WAIT_PARITY(mbar_smem_addr, phase_parity) do { \
    uint32_t _mbar = (uint32_t)(mbar_smem_addr); \
    uint32_t _parity = (uint32_t)(phase_parity); \
    uint32_t _done; \
    asm volatile("{\n\t.reg .pred p;\n\t" \
        "mbarrier.try_wait.parity.acquire.cta.shared::cta.b64 p, [%1], %2;\n\t" \
        "selp.b32 %0, 1, 0, p;\n\t}" : "=r"(_done) : "r"(_mbar), "r"(_parity) : "memory"); \
    if (!_done) { \
        asm volatile("{\n\t.reg .pred P1;\n\t" \
            "WAIT_LOOP_%=:\n\t" \
            "mbarrier.try_wait.parity.acquire.cta.shared::cta.b64 P1, [%0], %1, 0x989680;\n\t" \
            "@P1 bra.uni WAIT_DONE_%=;\n\t" \
            "bra.uni WAIT_LOOP_%=;\n\t" \
            "WAIT_DONE_%=:\n\t}" :: "r"(_mbar), "r"(_parity) : "memory"); \
    } \
} while (0)

// ================= fused prep kernel =================
// blocks [0,2048): pack w -> g_w8 blocks; [2048,2304): quantize x rows;
// [2304,2560): outlier GEMM + bias prefill of out.
__global__ __launch_bounds__(256) void prep_kernel(const float* __restrict__ x,
                                                   const int* __restrict__ w,
                                                   const int* __restrict__ oidx,
                                                   const float* __restrict__ ow,
                                                   const float* __restrict__ bias,
                                                   float* __restrict__ out) {
    __shared__ float s_owT[NOUT * 128];
    __shared__ float s_x[32 * NOUT];
    __shared__ float s_b[128];
    __shared__ int   s_oi[NOUT];
    __shared__ float red[8];
    __shared__ float s_scale;

    const int b = blockIdx.x;
    const int tid = threadIdx.x;

    if (b < 2048) {
        // ---------- pack: block (nt, c): 64 rows x 128 k -> 8KB ----------
        const int nt = b >> 5, c = b & 31;
#pragma unroll
        for (int t = 0; t < 2; t++) {
            int u = tid + t * 256;
            int r = u >> 3, cc = u & 7;
            const int* src = w + (size_t)(nt * 64 + r) * INF + c * 128 + cc * 16;
            int4 v0 = *(const int4*)(src);
            int4 v1 = *(const int4*)(src + 4);
            int4 v2 = *(const int4*)(src + 8);
            int4 v3 = *(const int4*)(src + 12);
            uint32_t a0 = __byte_perm(__byte_perm((uint32_t)v0.x, (uint32_t)v0.y, 0x0040),
                                      __byte_perm((uint32_t)v0.z, (uint32_t)v0.w, 0x0040), 0x5410);
            uint32_t a1 = __byte_perm(__byte_perm((uint32_t)v1.x, (uint32_t)v1.y, 0x0040),
                                      __byte_perm((uint32_t)v1.z, (uint32_t)v1.w, 0x0040), 0x5410);
            uint32_t a2 = __byte_perm(__byte_perm((uint32_t)v2.x, (uint32_t)v2.y, 0x0040),
                                      __byte_perm((uint32_t)v2.z, (uint32_t)v2.w, 0x0040), 0x5410);
            uint32_t a3 = __byte_perm(__byte_perm((uint32_t)v3.x, (uint32_t)v3.y, 0x0040),
                                      __byte_perm((uint32_t)v3.z, (uint32_t)v3.w, 0x0040), 0x5410);
            int8_t* dst = g_w8 + ((size_t)(nt * 32 + c) << 13) + r * 128 + ((cc ^ (r & 7)) << 4);
            *(uint4*)dst = make_uint4(a0, a1, a2, a3);
        }
    } else if (b < 2304) {
        // ---------- quantize row r ----------
        const int r = b - 2048;
        const int wid = tid >> 5, lid = tid & 31;

        const float4* xr = (const float4*)(x + (size_t)r * INF);
        float4 f[4];
#pragma unroll
        for (int t = 0; t < 4; t++) f[t] = xr[tid * 4 + t];

        if (tid < NOUT) s_oi[tid] = oidx[tid];
        __syncthreads();

        const int kbase = tid * 16;
        unsigned mz = 0;
#pragma unroll
        for (int j = 0; j < NOUT; j++) {
            unsigned d = (unsigned)(s_oi[j] - kbase);
            if (d < 16u) mz |= 1u << d;
        }
#pragma unroll
        for (int t = 0; t < 4; t++) {
            if (mz & (1u << (t * 4 + 0))) f[t].x = 0.0f;
            if (mz & (1u << (t * 4 + 1))) f[t].y = 0.0f;
            if (mz & (1u << (t * 4 + 2))) f[t].z = 0.0f;
            if (mz & (1u << (t * 4 + 3))) f[t].w = 0.0f;
        }

        float mx = 0.0f;
#pragma unroll
        for (int t = 0; t < 4; t++)
            mx = fmaxf(mx, fmaxf(fmaxf(fabsf(f[t].x), fabsf(f[t].y)),
                                 fmaxf(fabsf(f[t].z), fabsf(f[t].w))));
#pragma unroll
        for (int d = 16; d > 0; d >>= 1) mx = fmaxf(mx, __shfl_xor_sync(0xFFFFFFFFu, mx, d));
        if (lid == 0) red[wid] = mx;
        __syncthreads();
        if (tid == 0) {
            float m = red[0];
#pragma unroll
            for (int i = 1; i < 8; i++) m = fmaxf(m, red[i]);
            s_scale = m;
            g_xs[r] = m;
        }
        __syncthreads();
        const float r127 = 127.0f / fmaxf(s_scale, 1e-8f);

        uint32_t pk[4];
#pragma unroll
        for (int t = 0; t < 4; t++) {
            int q0 = min(max(__float2int_rn(f[t].x * r127), -127), 127);
            int q1 = min(max(__float2int_rn(f[t].y * r127), -127), 127);
            int q2 = min(max(__float2int_rn(f[t].z * r127), -127), 127);
            int q3 = min(max(__float2int_rn(f[t].w * r127), -127), 127);
            uint32_t p0 = __byte_perm((uint32_t)q0, (uint32_t)q1, 0x0040);
            uint32_t p1 = __byte_perm((uint32_t)q2, (uint32_t)q3, 0x0040);
            pk[t] = __byte_perm(p0, p1, 0x5410);
        }
        const int mt = r >> 7, rr = r & 127;
        const int c = tid >> 3, cp = tid & 7;
        int8_t* dst = g_xq + ((size_t)(mt * 32 + c) << 14) + rr * 128 + (((cp ^ (rr & 7))) << 4);
        *(uint4*)dst = make_uint4(pk[0], pk[1], pk[2], pk[3]);
    } else {
        // ---------- outlier + bias prefill: idx -> (obase, tbase) ----------
        const int idx = b - 2304;
        const int obase = (idx & 31) * 128;
        const int tbase = (idx >> 5) * 32;

        if (tid < NOUT) s_oi[tid] = oidx[tid];
        if (tid < 128)  s_b[tid] = bias[obase + tid];
        __syncthreads();

#pragma unroll
        for (int t = 0; t < 4; t++) {
            int i = tid + t * 256;
            int o = i >> 3, j4 = i & 7;
            float4 f = ((const float4*)ow)[(size_t)obase * 8 + i];
            s_owT[(j4 * 4 + 0) * 128 + o] = f.x;
            s_owT[(j4 * 4 + 1) * 128 + o] = f.y;
            s_owT[(j4 * 4 + 2) * 128 + o] = f.z;
            s_owT[(j4 * 4 + 3) * 128 + o] = f.w;
        }
#pragma unroll
        for (int t = 0; t < 4; t++) {
            int i = tid + t * 256;
            int r = i >> 5, j = i & 31;
            s_x[i] = x[(size_t)(tbase + r) * INF + s_oi[j]];
        }
        __syncthreads();

        const int ty = tid >> 5, tx = tid & 31;
        float acc[4][4];
#pragma unroll
        for (int tt = 0; tt < 4; tt++)
#pragma unroll
            for (int c = 0; c < 4; c++) acc[tt][c] = s_b[tx + c * 32];

#pragma unroll
        for (int j = 0; j < NOUT; j++) {
            float wv[4];
#pragma unroll
            for (int c = 0; c < 4; c++) wv[c] = s_owT[j * 128 + tx + c * 32];
#pragma unroll
            for (int tt = 0; tt < 4; tt++) {
                float xv = s_x[(ty * 4 + tt) * NOUT + j];
#pragma unroll
                for (int c = 0; c < 4; c++) acc[tt][c] += xv * wv[c];
            }
        }
#pragma unroll
        for (int tt = 0; tt < 4; tt++)
#pragma unroll
            for (int c = 0; c < 4; c++)
                out[(size_t)(tbase + ty * 4 + tt) * OUTF + obase + tx + c * 32] = acc[tt][c];
    }
}

// ================= persistent balanced GEMM =================
// 296 CTAs x 288 threads; warps 0-7 consume, warp 8 = bulk-copy producer.
// Each CTA owns a contiguous range of the 4096 flattened chunk-units.
#define SA_OFF(s) ((s) * 24576)
#define SB_OFF(s) ((s) * 24576 + 16384)
#define MBF_OFF   98304              // full[4]
#define MBE_OFF   (98304 + 32)       // empty[4]
#define SMEM_TOTAL (98304 + 128)

__global__ __launch_bounds__(288, 2) void gemm_kernel(const float* __restrict__ wscale,
                                                      float* __restrict__ out) {
    extern __shared__ char smem[];
    const uint32_t sb = smem_to_u32(smem);
    const int tid = threadIdx.x;
    const int lane = tid & 31, wid = tid >> 5;

    const int g0 = (int)(((long long)blockIdx.x * TOTCH) / NCTA);
    const int g1 = (int)(((long long)(blockIdx.x + 1) * TOTCH) / NCTA);

    if (tid == 0) {
#pragma unroll
        for (int s = 0; s < STAGES; s++) {
            MBARRIER_INIT(sb + MBF_OFF + s * 8, 1);
            MBARRIER_INIT(sb + MBE_OFF + s * 8, 256);
        }
    }
    __syncthreads();

    if (wid == 8) {
        // ---- producer: stream chunks g0..g1 through the 4-stage ring ----
        if (lane == 0) {
            int it = 0;
#pragma unroll 1
            for (int g = g0; g < g1; g++, it++) {
                const int fs = it & (STAGES - 1);
                if (it >= STAGES) {
                    MBARRIER_WAIT_PARITY(sb + MBE_OFF + fs * 8, ((it >> 2) - 1) & 1);
                }
                const int tile = g >> 5, k = g & 31;
                const int nt = tile >> 1, mt = tile & 1;
                const uint32_t mb = sb + MBF_OFF + fs * 8;
                MBARRIER_EXPECT_TX(mb, ABLK + BBLK);
                BULK_G2S(sb + SA_OFF(fs), g_xq + ((size_t)(mt * 32 + k) << 14), ABLK, mb);
                BULK_G2S(sb + SB_OFF(fs), g_w8 + ((size_t)(nt * 32 + k) << 13), BBLK, mb);
            }
        }
    } else {
        // ---- consumers: proven IMMA core; epilogue at each tile boundary ----
        const int wm = wid >> 1, wn = wid & 1;
        const float inv = 1.0f / 16129.0f;
        const int grp = lane >> 2, qid = lane & 3;

        int acc[2][4][4];
#pragma unroll
        for (int i = 0; i < 2; i++)
#pragma unroll
            for (int j = 0; j < 4; j++)
#pragma unroll
                for (int k = 0; k < 4; k++) acc[i][j][k] = 0;

        int it = 0;
#pragma unroll 1
        for (int g = g0; g < g1; g++, it++) {
            const int s = it & (STAGES - 1);
            MBARRIER_WAIT_PARITY(sb + MBF_OFF + s * 8, (it >> 2) & 1);

#pragma unroll
            for (int ksl = 0; ksl < 4; ksl++) {
                uint32_t a[2][4];
#pragma unroll
                for (int mf = 0; mf < 2; mf++) {
                    int row = wm * 32 + mf * 16 + (lane & 15);
                    int kc = 2 * ksl + (lane >> 4);
                    uint32_t ad = sb + SA_OFF(s) +
                                  (uint32_t)(row * 128 + ((kc ^ (row & 7)) << 4));
                    asm volatile("ldmatrix.sync.aligned.m8n8.x4.shared.b16 {%0,%1,%2,%3}, [%4];"
                        : "=r"(a[mf][0]), "=r"(a[mf][1]), "=r"(a[mf][2]), "=r"(a[mf][3])
                        : "r"(ad));
                }
                uint32_t b[2][4];
#pragma unroll
                for (int np = 0; np < 2; np++) {
                    int n = wn * 32 + np * 16 + (lane & 7) + ((lane >> 4) << 3);
                    int kc = 2 * ksl + ((lane >> 3) & 1);
                    uint32_t bd = sb + SB_OFF(s) +
                                  (uint32_t)(n * 128 + ((kc ^ (n & 7)) << 4));
                    asm volatile("ldmatrix.sync.aligned.m8n8.x4.shared.b16 {%0,%1,%2,%3}, [%4];"
                        : "=r"(b[np][0]), "=r"(b[np][1]), "=r"(b[np][2]), "=r"(b[np][3])
                        : "r"(bd));
                }
#pragma unroll
                for (int mf = 0; mf < 2; mf++)
#pragma unroll
                    for (int nf = 0; nf < 4; nf++) {
                        uint32_t b0 = b[nf >> 1][(nf & 1) * 2];
                        uint32_t b1 = b[nf >> 1][(nf & 1) * 2 + 1];
                        asm volatile(
                            "mma.sync.aligned.m16n8k32.row.col.s32.s8.s8.s32 "
                            "{%0,%1,%2,%3}, {%4,%5,%6,%7}, {%8,%9}, {%0,%1,%2,%3};"
                            : "+r"(acc[mf][nf][0]), "+r"(acc[mf][nf][1]),
                              "+r"(acc[mf][nf][2]), "+r"(acc[mf][nf][3])
                            : "r"(a[mf][0]), "r"(a[mf][1]), "r"(a[mf][2]), "r"(a[mf][3]),
                              "r"(b0), "r"(b1));
                    }
            }
            MBARRIER_ARRIVE(sb + MBE_OFF + s * 8);

            // ---- epilogue at tile boundary or range end ----
            if (g + 1 == g1 || ((g + 1) & 31) == 0) {
                const int tile = g >> 5;
                const int nbase = (tile >> 1) * BN, mbase = (tile & 1) * BM;
#pragma unroll
                for (int mf = 0; mf < 2; mf++) {
                    const int m0 = mbase + wm * 32 + mf * 16 + grp;
                    const float s0 = g_xs[m0] * inv;
                    const float s1 = g_xs[m0 + 8] * inv;
#pragma unroll
                    for (int nf = 0; nf < 4; nf++) {
                        const int o = nbase + wn * 32 + nf * 8 + qid * 2;
                        const float2 wsv = *(const float2*)(wscale + o);
                        float* p0 = out + (size_t)m0 * OUTF + o;
                        float* p1 = out + (size_t)(m0 + 8) * OUTF + o;
                        atomicAdd(p0,     (float)acc[mf][nf][0] * (s0 * wsv.x));
                        atomicAdd(p0 + 1, (float)acc[mf][nf][1] * (s0 * wsv.y));
                        atomicAdd(p1,     (float)acc[mf][nf][2] * (s1 * wsv.x));
                        atomicAdd(p1 + 1, (float)acc[mf][nf][3] * (s1 * wsv.y));
                    }
                }
#pragma unroll
                for (int i = 0; i < 2; i++)
#pragma unroll
                    for (int j = 0; j < 4; j++)
#pragma unroll
                        for (int k = 0; k < 4; k++) acc[i][j][k] = 0;
            }
        }
    }
}

// ---------------- launch: default stream only ----------------
extern "C" void kernel_launch(void* const* d_in, const int* in_sizes, int n_in,
                              void* d_out, int out_size) {
    const float* x    = (const float*)d_in[0];
    const int*   w    = (const int*)d_in[1];
    const float* ws   = (const float*)d_in[2];
    const int*   oidx = (const int*)d_in[3];
    const float* ow   = (const float*)d_in[4];
    const float* bias = (const float*)d_in[5];
    float* out = (float*)d_out;

    cudaFuncSetAttribute(gemm_kernel, cudaFuncAttributeMaxDynamicSharedMemorySize, SMEM_TOTAL);

    prep_kernel<<<2560, 256>>>(x, w, oidx, ow, bias, out);
    gemm_kernel<<<NCTA, 288, SMEM_TOTAL>>>(ws, out);
}